// round 1
// baseline (speedup 1.0000x reference)
#include <cuda_runtime.h>
#include <cstdint>

// Problem constants
#define B_     64
#define T_     16
#define IMG_   84
#define P_     7
#define GH_    12
#define GW_    12
#define NS_    144      // GH*GW
#define GD_    8        // T/TUBE
#define TUBE_  2
#define K_     98       // TUBE * P*P
#define E_     1024
#define NTOK_  1152     // GD*NS
#define M_     73728    // B * NTOK

// Scratch (device globals; allocation is forbidden)
__device__ float g_tub[(size_t)K_ * M_];   // [k][m]  28.9 MB
__device__ float g_Wt[(size_t)K_ * E_];    // [k][e]

// ---------------------------------------------------------------------------
// packed f32x2 helpers (ptxas will not auto-fuse FFMA2; must come from PTX)
// ---------------------------------------------------------------------------
__device__ __forceinline__ unsigned long long pack2(float x, float y) {
    unsigned long long r;
    asm("mov.b64 %0, {%1, %2};" : "=l"(r) : "f"(x), "f"(y));
    return r;
}
__device__ __forceinline__ void fma2(unsigned long long& acc,
                                     unsigned long long a,
                                     unsigned long long b) {
    asm("fma.rn.f32x2 %0, %1, %2, %0;" : "+l"(acc) : "l"(a), "l"(b));
}
__device__ __forceinline__ float2 unpack2(unsigned long long v) {
    float2 r;
    asm("mov.b64 {%0, %1}, %2;" : "=f"(r.x), "=f"(r.y) : "l"(v));
    return r;
}

// ---------------------------------------------------------------------------
// 1) Gather: video [B,T,1,84,84] -> g_tub [K][M]   (K-major so GEMM loads coalesce)
//    block = one (b,t) frame. token m = b*1152 + (t/2)*144 + s, k = (t%2)*49 + pi*7+pj
// ---------------------------------------------------------------------------
__global__ void gather_kernel(const float* __restrict__ video) {
    __shared__ float frame[IMG_ * IMG_];       // 28224 B
    int bt = blockIdx.x;
    int b  = bt >> 4;
    int t  = bt & 15;
    const float* src = video + (size_t)bt * (IMG_ * IMG_);
    for (int i = threadIdx.x; i < IMG_ * IMG_; i += blockDim.x)
        frame[i] = src[i];
    __syncthreads();

    int d = t >> 1, ts = t & 1;
    int mbase = b * NTOK_ + d * NS_;
    int kbase = ts * 49;

    for (int i = threadIdx.x; i < 49 * NS_; i += blockDim.x) {
        int k  = i / NS_;
        int s  = i - k * NS_;
        int pi = k / P_, pj = k - pi * P_;
        int h  = s / GW_, w = s - h * GW_;
        float v = frame[(h * P_ + pi) * IMG_ + (w * P_ + pj)];
        g_tub[(size_t)(kbase + k) * M_ + mbase + s] = v;   // 576B-contig runs per k
    }
}

// ---------------------------------------------------------------------------
// 2) Transpose W [E][K] -> g_Wt [K][E]
// ---------------------------------------------------------------------------
__global__ void wt_kernel(const float* __restrict__ W) {
    __shared__ float tile[32][33];
    int e0 = blockIdx.x * 32;
    int k0 = blockIdx.y * 32;
    int tx = threadIdx.x, ty = threadIdx.y;

    int k = k0 + tx;                       // coalesced read along K
    if (k < K_) tile[ty][tx] = W[(size_t)(e0 + ty) * K_ + k];
    __syncthreads();
    int ko = k0 + ty, eo = e0 + tx;        // coalesced write along E
    if (ko < K_) g_Wt[(size_t)ko * E_ + eo] = tile[tx][ty];
}

// ---------------------------------------------------------------------------
// 3) GEMM: out[m][e] = sum_k g_tub[k][m]*g_Wt[k][e] + bias[e] + pos[m%1152][e]
//    128x128 CTA tile, 8x8 per thread, fma.rn.f32x2 mainloop
// ---------------------------------------------------------------------------
#define MT 128
#define ET 128
#define KC 32

__global__ __launch_bounds__(256, 2)
void gemm_kernel(const float* __restrict__ bias,
                 const float* __restrict__ pos,
                 float* __restrict__ out) {
    __shared__ float sT[KC][MT];   // 16 KB
    __shared__ float sW[KC][ET];   // 16 KB

    int tid = threadIdx.x;
    int tx = tid & 15;             // embed group
    int ty = tid >> 4;             // token group
    int m0 = blockIdx.x * MT;
    int e0 = blockIdx.y * ET;

    unsigned long long acc[8][4];
#pragma unroll
    for (int i = 0; i < 8; ++i)
#pragma unroll
        for (int j = 0; j < 4; ++j) acc[i][j] = 0ull;

#pragma unroll 1
    for (int c = 0; c < 4; ++c) {
        int kc0 = c * KC;
        __syncthreads();
        // stage 32 K-rows of both operands (float4, fully coalesced, zero-pad K>=98)
#pragma unroll
        for (int r = 0; r < 4; ++r) {
            int li = tid + r * 256;        // 0..1023 float4 slots
            int kr = li >> 5;              // 0..31
            int c4 = li & 31;              // 0..31
            int k  = kc0 + kr;
            float4 vT = make_float4(0.f, 0.f, 0.f, 0.f);
            float4 vW = vT;
            if (k < K_) {
                vT = *(const float4*)(g_tub + (size_t)k * M_ + m0 + c4 * 4);
                vW = *(const float4*)(g_Wt  + (size_t)k * E_ + e0 + c4 * 4);
            }
            *(float4*)&sT[kr][c4 * 4] = vT;
            *(float4*)&sW[kr][c4 * 4] = vW;
        }
        __syncthreads();

#define STEP(kk)                                                           \
        {                                                                  \
            float4 a0 = *(const float4*)&sT[(kk)][ty * 8];                 \
            float4 a1 = *(const float4*)&sT[(kk)][ty * 8 + 4];             \
            ulonglong2 b01 = *(const ulonglong2*)&sW[(kk)][tx * 8];        \
            ulonglong2 b23 = *(const ulonglong2*)&sW[(kk)][tx * 8 + 4];    \
            unsigned long long bb0 = b01.x, bb1 = b01.y;                   \
            unsigned long long bb2 = b23.x, bb3 = b23.y;                   \
            float av[8] = {a0.x, a0.y, a0.z, a0.w, a1.x, a1.y, a1.z, a1.w};\
            _Pragma("unroll")                                              \
            for (int i = 0; i < 8; ++i) {                                  \
                unsigned long long ad = pack2(av[i], av[i]);               \
                fma2(acc[i][0], ad, bb0);                                  \
                fma2(acc[i][1], ad, bb1);                                  \
                fma2(acc[i][2], ad, bb2);                                  \
                fma2(acc[i][3], ad, bb3);                                  \
            }                                                              \
        }

        if (c < 3) {
#pragma unroll
            for (int k = 0; k < KC; ++k) { STEP(k) }
        } else {
            // tail: only k = 96, 97 are real
#pragma unroll
            for (int k = 0; k < 2; ++k) { STEP(k) }
        }
#undef STEP
    }

    // epilogue: + bias + pos_embed, float4 stores
    float4 bia0 = *(const float4*)(bias + e0 + tx * 8);
    float4 bia1 = *(const float4*)(bias + e0 + tx * 8 + 4);

#pragma unroll
    for (int i = 0; i < 8; ++i) {
        int m = m0 + ty * 8 + i;
        int n = m % NTOK_;
        const float* pp = pos + (size_t)n * E_ + e0 + tx * 8;
        float4 p0 = *(const float4*)pp;
        float4 p1 = *(const float4*)(pp + 4);
        float2 v0 = unpack2(acc[i][0]);
        float2 v1 = unpack2(acc[i][1]);
        float2 v2 = unpack2(acc[i][2]);
        float2 v3 = unpack2(acc[i][3]);
        float4 o0 = make_float4(v0.x + bia0.x + p0.x, v0.y + bia0.y + p0.y,
                                v1.x + bia0.z + p0.z, v1.y + bia0.w + p0.w);
        float4 o1 = make_float4(v2.x + bia1.x + p1.x, v2.y + bia1.y + p1.y,
                                v3.x + bia1.z + p1.z, v3.y + bia1.w + p1.w);
        float* op = out + (size_t)m * E_ + e0 + tx * 8;
        *(float4*)op       = o0;
        *(float4*)(op + 4) = o1;
    }
}

// ---------------------------------------------------------------------------
extern "C" void kernel_launch(void* const* d_in, const int* in_sizes, int n_in,
                              void* d_out, int out_size) {
    const float* video = (const float*)d_in[0];   // [64,16,1,84,84]
    const float* W     = (const float*)d_in[1];   // [1024,98]
    const float* bias  = (const float*)d_in[2];   // [1024]
    const float* pos   = (const float*)d_in[3];   // [1,1152,1024]
    float* out         = (float*)d_out;           // [64,1152,1024]

    gather_kernel<<<B_ * T_, 256>>>(video);
    wt_kernel<<<dim3(E_ / 32, (K_ + 31) / 32), dim3(32, 32)>>>(W);
    gemm_kernel<<<dim3(M_ / MT, E_ / ET), 256>>>(bias, pos, out);
}